// round 4
// baseline (speedup 1.0000x reference)
#include <cuda_runtime.h>
#include <cuda_bf16.h>
#include <cstdint>

// ---------------------------------------------------------------------------
// VQVAE forward on GB300, round 1: everything as fp32 GEMMs (channels-last).
// Shapes: B=16 L=2048 E=128 H=256 D=64 Kc=512 V=4096, M = B*L = 32768.
// Output buffer: [logits (M*V)] [loss (1)] [codes (M)]  as float32.
// ---------------------------------------------------------------------------

#define BATCH 16
#define SEQL  2048
#define LPAD  2050
#define EMB   128
#define HID   256
#define DCODE 64
#define KCODE 512
#define VOCAB 4096
#define MROWS (BATCH * SEQL)   // 32768

// ---------------- scratch (device globals; zero-initialized) ----------------
__device__ float g_P0 [BATCH * LPAD * EMB];    // padded embedded input
__device__ float g_H1 [BATCH * LPAD * HID];    // padded conv1 out
__device__ float g_H2 [BATCH * SEQL * HID];    // conv2 out
__device__ float g_ZE [BATCH * SEQL * DCODE];  // encoder output z_e
__device__ float g_S  [MROWS * KCODE];         // VQ scores (-2 z.c + |c|^2)
__device__ int   g_CODES[MROWS];
__device__ float g_HD1[BATCH * LPAD * HID];    // padded dec conv1 out
__device__ float g_HD2[BATCH * SEQL * HID];
__device__ float g_HD3[BATCH * SEQL * EMB];
__device__ float g_PART[4096];

__device__ float g_W1p [3 * EMB * HID];
__device__ float g_W2p [3 * HID * HID];
__device__ float g_W3p [HID * DCODE];
__device__ float g_DW1p[DCODE * HID];
__device__ float g_DW2p[3 * HID * HID];
__device__ float g_DW3p[HID * EMB];
__device__ float g_OWp [EMB * VOCAB];
__device__ float g_CBt [DCODE * KCODE];        // -2 * codebook^T
__device__ float g_CNRM[KCODE];

// ---------------------------- weight prepack --------------------------------
__global__ void pack_k3(const float* __restrict__ w, float* __restrict__ wp,
                        int Cout, int Cin) {
    int i = blockIdx.x * blockDim.x + threadIdx.x;
    int tot = Cout * Cin * 3;
    if (i >= tot) return;
    int j = i % 3;
    int e = (i / 3) % Cin;
    int h = i / (3 * Cin);
    wp[(j * Cin + e) * Cout + h] = w[i];
}

__global__ void pack_k1(const float* __restrict__ w, float* __restrict__ wp,
                        int Cout, int Cin) {
    int i = blockIdx.x * blockDim.x + threadIdx.x;
    if (i >= Cout * Cin) return;
    int e = i % Cin;
    int h = i / Cin;
    wp[e * Cout + h] = w[i];
}

__global__ void pack_cb(const float* __restrict__ cb, float* __restrict__ cbt,
                        float* __restrict__ cnrm) {
    int k = blockIdx.x * blockDim.x + threadIdx.x;
    if (k >= KCODE) return;
    float s = 0.f;
    for (int d = 0; d < DCODE; d++) {
        float v = cb[k * DCODE + d];
        cbt[d * KCODE + k] = -2.0f * v;
        s += v * v;
    }
    cnrm[k] = s;
}

// ---------------------------- embedding + pads ------------------------------
__global__ void embed_k(const int* __restrict__ x, const float* __restrict__ emb,
                        float* __restrict__ P0) {
    int i = blockIdx.x * blockDim.x + threadIdx.x;
    const int tot = BATCH * LPAD * EMB;
    if (i >= tot) return;
    int e  = i % EMB;
    int r  = i / EMB;
    int rr = r % LPAD;
    int b  = r / LPAD;
    float v = 0.f;
    if (rr >= 1 && rr <= SEQL)
        v = emb[(long)x[b * SEQL + rr - 1] * EMB + e];
    P0[i] = v;
}

__global__ void zeropad_k(float* __restrict__ H1, float* __restrict__ HD1) {
    // zero rows 0 and LPAD-1 of each batch for both padded HID buffers
    int i = blockIdx.x * blockDim.x + threadIdx.x;
    const int per = BATCH * 2 * HID;
    if (i >= per * 2) return;
    float* buf = (i < per) ? H1 : HD1;
    int j = i % per;
    int c = j % HID;
    int w = j / HID;          // 0..31 -> (batch, which end)
    int b = w >> 1;
    int row = (w & 1) ? (LPAD - 1) : 0;
    buf[((long)b * LPAD + row) * HID + c] = 0.f;
}

// ------------------------------- SGEMM --------------------------------------
// C[m][n] = act( sum_k Arow(m)[k] * B[k][n] + bias[n] )
// Arow(m) = A + aidx[m]*K                      (if aidx)
//         = A + (m>>11)*aBS + (m&2047)*aRS     (otherwise)
// Cptr(m) = C + (m>>11)*cBS + ((m&2047)+cPad)*N
// BM=BN=128, BK=8, 256 threads, 8x8 per thread.
__global__ __launch_bounds__(256, 2) void sgemm_k(
    const float* __restrict__ A, const float* __restrict__ B,
    const float* __restrict__ bias, float* __restrict__ C,
    int M, int N, int K,
    long aBS, int aRS, const int* __restrict__ aidx,
    long cBS, int cPad, int relu)
{
    __shared__ float As[8][132];
    __shared__ float Bs[8][128];

    int t  = threadIdx.x;
    int m0 = blockIdx.y * 128;
    int n0 = blockIdx.x * 128;

    // A-load mapping: thread -> (row, k-quad)
    int ar = t >> 1;
    int ak = (t & 1) * 4;
    long mA = m0 + ar;
    const float* Ap;
    if (aidx) {
        Ap = A + (long)aidx[mA] * K;
    } else {
        long bb = mA >> 11, ll = mA & 2047;
        Ap = A + bb * aBS + ll * (long)aRS;
    }

    // B-load mapping
    int br = t >> 5;
    int bc = (t & 31) * 4;
    int nb = n0 + bc;
    bool bok = (nb < N);
    const float* Bg = B + (long)br * N + nb;

    int ty = t >> 4;   // 0..15 -> m sub-tile
    int tx = t & 15;   // 0..15 -> n sub-tile

    float acc[8][8];
#pragma unroll
    for (int i = 0; i < 8; i++)
#pragma unroll
        for (int j = 0; j < 8; j++) acc[i][j] = 0.f;

    for (int kt = 0; kt < K; kt += 8) {
        float4 aV = *(const float4*)(Ap + kt + ak);
        float4 bV = make_float4(0.f, 0.f, 0.f, 0.f);
        if (bok) bV = *(const float4*)(Bg + (long)kt * N);

        __syncthreads();
        As[ak + 0][ar] = aV.x;
        As[ak + 1][ar] = aV.y;
        As[ak + 2][ar] = aV.z;
        As[ak + 3][ar] = aV.w;
        *(float4*)&Bs[br][bc] = bV;
        __syncthreads();

#pragma unroll
        for (int kk = 0; kk < 8; kk++) {
            float a0[8], b0[8];
            *(float4*)&a0[0] = *(const float4*)&As[kk][ty * 8];
            *(float4*)&a0[4] = *(const float4*)&As[kk][ty * 8 + 4];
            *(float4*)&b0[0] = *(const float4*)&Bs[kk][tx * 8];
            *(float4*)&b0[4] = *(const float4*)&Bs[kk][tx * 8 + 4];
#pragma unroll
            for (int i = 0; i < 8; i++)
#pragma unroll
                for (int j = 0; j < 8; j++)
                    acc[i][j] = fmaf(a0[i], b0[j], acc[i][j]);
        }
    }

#pragma unroll
    for (int i = 0; i < 8; i++) {
        long m = m0 + ty * 8 + i;
        long bb = m >> 11, ll = m & 2047;
        float* Cp = C + bb * cBS + (ll + cPad) * (long)N;
#pragma unroll
        for (int j = 0; j < 8; j++) {
            int n = n0 + tx * 8 + j;
            if (n < N) {
                float v = acc[i][j] + bias[n];
                if (relu) v = fmaxf(v, 0.f);
                Cp[n] = v;
            }
        }
    }
}

// --------------------------- VQ argmin + loss --------------------------------
__global__ __launch_bounds__(256) void argmin_k(
    const float* __restrict__ S, const float* __restrict__ ZE,
    int* __restrict__ codes, float* __restrict__ codesF,
    float* __restrict__ partials)
{
    int lane = threadIdx.x & 31;
    int wid  = threadIdx.x >> 5;
    int m    = blockIdx.x * 8 + wid;

    const float* Sp = S + (long)m * KCODE;
    float best = 3.4e38f;
    int   bi   = KCODE;
#pragma unroll
    for (int i = 0; i < 16; i++) {
        int c = lane + i * 32;
        float v = Sp[c];
        if (v < best) { best = v; bi = c; }
    }
#pragma unroll
    for (int off = 16; off; off >>= 1) {
        float ob = __shfl_down_sync(0xffffffff, best, off);
        int   oi = __shfl_down_sync(0xffffffff, bi, off);
        if (ob < best || (ob == best && oi < bi)) { best = ob; bi = oi; }
    }

    const float* Zp = ZE + (long)m * DCODE;
    float zn = 0.f;
#pragma unroll
    for (int i = 0; i < 2; i++) {
        float v = Zp[lane + i * 32];
        zn = fmaf(v, v, zn);
    }
#pragma unroll
    for (int off = 16; off; off >>= 1)
        zn += __shfl_down_sync(0xffffffff, zn, off);

    __shared__ float sPart[8];
    if (lane == 0) {
        codes[m] = bi;
        if (codesF) codesF[m] = (float)bi;
        sPart[wid] = zn + best;      // ||z||^2 + (-2 z.c + ||c||^2) = dist
    }
    __syncthreads();
    if (threadIdx.x == 0) {
        float s = 0.f;
        for (int i = 0; i < 8; i++) s += sPart[i];
        partials[blockIdx.x] = s;
    }
}

__global__ void loss_k(const float* __restrict__ partials, float* __restrict__ out) {
    __shared__ float sh[256];
    float s = 0.f;
    for (int i = threadIdx.x; i < 4096; i += 256) s += partials[i];
    sh[threadIdx.x] = s;
    __syncthreads();
    for (int off = 128; off; off >>= 1) {
        if (threadIdx.x < off) sh[threadIdx.x] += sh[threadIdx.x + off];
        __syncthreads();
    }
    if (threadIdx.x == 0)
        out[0] = 0.1f * sh[0] / (float)(MROWS * DCODE);
}

// ------------------------------- launch -------------------------------------
static float* symf(const void* s) {
    void* p = nullptr;
    cudaGetSymbolAddress(&p, s);
    return (float*)p;
}

static void run_sgemm(const float* A, const float* B, const float* bias, float* C,
                      int M, int N, int K, long aBS, int aRS, const int* aidx,
                      long cBS, int cPad, int relu)
{
    dim3 grid((N + 127) / 128, M / 128);
    sgemm_k<<<grid, 256>>>(A, B, bias, C, M, N, K, aBS, aRS, aidx, cBS, cPad, relu);
}

extern "C" void kernel_launch(void* const* d_in, const int* in_sizes, int n_in,
                              void* d_out, int out_size)
{
    const int*   x        = (const int*)  d_in[0];
    const float* tokenEmb = (const float*)d_in[1];
    const float* ew1 = (const float*)d_in[2];  const float* eb1 = (const float*)d_in[3];
    const float* ew2 = (const float*)d_in[4];  const float* eb2 = (const float*)d_in[5];
    const float* ew3 = (const float*)d_in[6];  const float* eb3 = (const float*)d_in[7];
    const float* cb  = (const float*)d_in[8];
    const float* dw1 = (const float*)d_in[9];  const float* db1 = (const float*)d_in[10];
    const float* dw2 = (const float*)d_in[11]; const float* db2 = (const float*)d_in[12];
    const float* dw3 = (const float*)d_in[13]; const float* db3 = (const float*)d_in[14];
    const float* outW = (const float*)d_in[15];
    const float* outB = (const float*)d_in[16];

    float* out = (float*)d_out;

    float* P0  = symf(g_P0);
    float* H1  = symf(g_H1);
    float* H2  = symf(g_H2);
    float* ZE  = symf(g_ZE);
    float* S   = symf(g_S);
    int*   CODES = (int*)symf(g_CODES);
    float* HD1 = symf(g_HD1);
    float* HD2 = symf(g_HD2);
    float* HD3 = symf(g_HD3);
    float* PART = symf(g_PART);
    float* W1p = symf(g_W1p);
    float* W2p = symf(g_W2p);
    float* W3p = symf(g_W3p);
    float* DW1p = symf(g_DW1p);
    float* DW2p = symf(g_DW2p);
    float* DW3p = symf(g_DW3p);
    float* OWp = symf(g_OWp);
    float* CBt = symf(g_CBt);
    float* CNRM = symf(g_CNRM);

    // ---- weight prepack ----
    pack_k3<<<(HID * EMB * 3 + 255) / 256, 256>>>(ew1, W1p, HID, EMB);
    pack_k3<<<(HID * HID * 3 + 255) / 256, 256>>>(ew2, W2p, HID, HID);
    pack_k1<<<(DCODE * HID + 255) / 256, 256>>>(ew3, W3p, DCODE, HID);
    pack_k1<<<(HID * DCODE + 255) / 256, 256>>>(dw1, DW1p, HID, DCODE);
    pack_k3<<<(HID * HID * 3 + 255) / 256, 256>>>(dw2, DW2p, HID, HID);
    pack_k1<<<(EMB * HID + 255) / 256, 256>>>(dw3, DW3p, EMB, HID);
    pack_k1<<<(VOCAB * EMB + 255) / 256, 256>>>(outW, OWp, VOCAB, EMB);
    pack_cb<<<2, 256>>>(cb, CBt, CNRM);

    // ---- embedding (with pad rows), zero pads of HID padded buffers ----
    embed_k<<<(BATCH * LPAD * EMB + 255) / 256, 256>>>(x, tokenEmb, P0);
    zeropad_k<<<(BATCH * 2 * HID * 2 + 255) / 256, 256>>>(H1, HD1);

    // ---- encoder ----
    run_sgemm(P0, W1p, eb1, H1, MROWS, HID, 3 * EMB,
              (long)LPAD * EMB, EMB, nullptr, (long)LPAD * HID, 1, 1);
    run_sgemm(H1, W2p, eb2, H2, MROWS, HID, 3 * HID,
              (long)LPAD * HID, HID, nullptr, (long)SEQL * HID, 0, 1);
    run_sgemm(H2, W3p, eb3, ZE, MROWS, DCODE, HID,
              (long)SEQL * HID, HID, nullptr, (long)SEQL * DCODE, 0, 0);

    // ---- VQ: scores = -2 z.c + |c|^2 (as GEMM with bias), then argmin ----
    run_sgemm(ZE, CBt, CNRM, S, MROWS, KCODE, DCODE,
              (long)SEQL * DCODE, DCODE, nullptr, (long)SEQL * KCODE, 0, 0);

    const long LOGN = (long)MROWS * VOCAB;
    bool full_out = ((long)out_size >= LOGN + 1 + MROWS);
    float* codesF = full_out ? (out + LOGN + 1) : nullptr;
    argmin_k<<<MROWS / 8, 256>>>(S, ZE, CODES, codesF, PART);
    if (full_out) loss_k<<<1, 256>>>(PART, out + LOGN);

    // ---- decoder (z_q gathered from codebook via CODES in dconv1 A-path) ----
    run_sgemm(cb, DW1p, db1, HD1, MROWS, HID, DCODE,
              0, 0, CODES, (long)LPAD * HID, 1, 1);
    run_sgemm(HD1, DW2p, db2, HD2, MROWS, HID, 3 * HID,
              (long)LPAD * HID, HID, nullptr, (long)SEQL * HID, 0, 1);
    run_sgemm(HD2, DW3p, db3, HD3, MROWS, EMB, HID,
              (long)SEQL * HID, HID, nullptr, (long)SEQL * EMB, 0, 1);

    // ---- vocab projection straight into d_out ----
    run_sgemm(HD3, OWp, outB, out, MROWS, VOCAB, EMB,
              (long)SEQL * EMB, EMB, nullptr, (long)SEQL * VOCAB, 0, 0);
}

// round 7
// speedup vs baseline: 1.9539x; 1.9539x over previous
#include <cuda_runtime.h>
#include <cuda_bf16.h>
#include <cstdint>

// ---------------------------------------------------------------------------
// VQVAE forward on GB300, round 4: GEMMs on tensor cores via mma.sync tf32.
//   Encoder convs + VQ scores: 3xTF32 split (fp32-equivalent accuracy; the
//   VQ argmin gaps are ~1e-6 abs and a single code flip fails rel_err).
//   Decoder convs + vocab projection: 1xTF32 (codes are exact ints; logits
//   elementwise err ~2e-4 << 1e-3).
// Shapes: B=16 L=2048 E=128 H=256 D=64 Kc=512 V=4096, M = B*L = 32768.
// Output: [logits (M*V)] [loss (1)] [codes (M)] as float32.
// ---------------------------------------------------------------------------

#define BATCH 16
#define SEQL  2048
#define LPAD  2050
#define EMB   128
#define HID   256
#define DCODE 64
#define KCODE 512
#define VOCAB 4096
#define MROWS (BATCH * SEQL)   // 32768

// ---------------- scratch (device globals) ----------------------------------
__device__ float g_P0 [BATCH * LPAD * EMB];
__device__ float g_H1 [BATCH * LPAD * HID];
__device__ float g_H2 [BATCH * SEQL * HID];
__device__ float g_ZE [BATCH * SEQL * DCODE];
__device__ float g_S  [MROWS * KCODE];
__device__ int   g_CODES[MROWS];
__device__ float g_HD1[BATCH * LPAD * HID];
__device__ float g_HD2[BATCH * SEQL * HID];
__device__ float g_HD3[BATCH * SEQL * EMB];
__device__ float g_PART[4096];

// packed weights, tf32 hi (+lo for the split path)
__device__ float g_W1h[3 * EMB * HID],  g_W1l[3 * EMB * HID];
__device__ float g_W2h[3 * HID * HID],  g_W2l[3 * HID * HID];
__device__ float g_W3h[HID * DCODE],    g_W3l[HID * DCODE];
__device__ float g_CBh[DCODE * KCODE],  g_CBl[DCODE * KCODE];
__device__ float g_CNRM[KCODE];
__device__ float g_DW1h[DCODE * HID];
__device__ float g_DW2h[3 * HID * HID];
__device__ float g_DW3h[HID * EMB];
__device__ float g_OWh [EMB * VOCAB];

// ------------------------------ helpers -------------------------------------
__device__ __forceinline__ uint32_t f2tf(float v) {
    uint32_t r;
    asm("cvt.rna.tf32.f32 %0, %1;" : "=r"(r) : "f"(v));
    return r;
}

__device__ __forceinline__ void mma8(float* c, const uint32_t* a, const uint32_t* b) {
    asm volatile(
        "mma.sync.aligned.m16n8k8.row.col.f32.tf32.tf32.f32 "
        "{%0,%1,%2,%3}, {%4,%5,%6,%7}, {%8,%9}, {%0,%1,%2,%3};\n"
        : "+f"(c[0]), "+f"(c[1]), "+f"(c[2]), "+f"(c[3])
        : "r"(a[0]), "r"(a[1]), "r"(a[2]), "r"(a[3]), "r"(b[0]), "r"(b[1]));
}

// ---------------------------- weight prepack --------------------------------
// k3 conv weight (Cout,Cin,3) -> [3*Cin][Cout] row-major, tf32 hi (+lo)
__global__ void pack_k3(const float* __restrict__ w, float* __restrict__ hi,
                        float* __restrict__ lo, int Cout, int Cin) {
    int i = blockIdx.x * blockDim.x + threadIdx.x;
    int tot = Cout * Cin * 3;
    if (i >= tot) return;
    int j = i % 3;
    int e = (i / 3) % Cin;
    int h = i / (3 * Cin);
    int dst = (j * Cin + e) * Cout + h;
    float v = w[i];
    uint32_t hb = f2tf(v);
    hi[dst] = __uint_as_float(hb);
    if (lo) lo[dst] = __uint_as_float(f2tf(v - __uint_as_float(hb)));
}

__global__ void pack_k1(const float* __restrict__ w, float* __restrict__ hi,
                        float* __restrict__ lo, int Cout, int Cin) {
    int i = blockIdx.x * blockDim.x + threadIdx.x;
    if (i >= Cout * Cin) return;
    int e = i % Cin;
    int h = i / Cin;
    int dst = e * Cout + h;
    float v = w[i];
    uint32_t hb = f2tf(v);
    hi[dst] = __uint_as_float(hb);
    if (lo) lo[dst] = __uint_as_float(f2tf(v - __uint_as_float(hb)));
}

// codebook -> B = -2*cb^T (tf32 hi/lo) and bias = ||c||^2 (fp32 exact)
__global__ void pack_cb(const float* __restrict__ cb, float* __restrict__ hi,
                        float* __restrict__ lo, float* __restrict__ cnrm) {
    int k = blockIdx.x * blockDim.x + threadIdx.x;
    if (k >= KCODE) return;
    float s = 0.f;
    for (int d = 0; d < DCODE; d++) {
        float v = cb[k * DCODE + d];
        float b = -2.0f * v;
        uint32_t hb = f2tf(b);
        hi[d * KCODE + k] = __uint_as_float(hb);
        lo[d * KCODE + k] = __uint_as_float(f2tf(b - __uint_as_float(hb)));
        s += v * v;
    }
    cnrm[k] = s;
}

// ---------------------------- embedding + pads ------------------------------
__global__ void embed_k(const int* __restrict__ x, const float* __restrict__ emb,
                        float* __restrict__ P0) {
    int i = blockIdx.x * blockDim.x + threadIdx.x;
    const int tot = BATCH * LPAD * EMB;
    if (i >= tot) return;
    int e  = i % EMB;
    int r  = i / EMB;
    int rr = r % LPAD;
    int b  = r / LPAD;
    float v = 0.f;
    if (rr >= 1 && rr <= SEQL)
        v = emb[(long)x[b * SEQL + rr - 1] * EMB + e];
    P0[i] = v;
}

__global__ void zeropad_k(float* __restrict__ H1, float* __restrict__ HD1) {
    int i = blockIdx.x * blockDim.x + threadIdx.x;
    const int per = BATCH * 2 * HID;
    if (i >= per * 2) return;
    float* buf = (i < per) ? H1 : HD1;
    int j = i % per;
    int c = j % HID;
    int w = j / HID;
    int b = w >> 1;
    int row = (w & 1) ? (LPAD - 1) : 0;
    buf[((long)b * LPAD + row) * HID + c] = 0.f;
}

// ------------------------------ TF32 GEMM ------------------------------------
// C[m][n] = act( sum_k Arow(m)[k]*B[k][n] + bias[n] ), tile 128x128x16,
// 256 threads = 8 warps (2x4), warp tile 64x32, mma.sync m16n8k8 tf32.
// SPLIT: 3xTF32 (hi*hi + hi*lo + lo*hi) for fp32-equivalent accuracy.
// Smem row stride 136 floats (8 mod 32) => conflict-free fragment loads.
template<bool SPLIT>
__global__ __launch_bounds__(256) void mma_gemm(
    const float* __restrict__ A,
    const float* __restrict__ Bh, const float* __restrict__ Bl,
    const float* __restrict__ bias, float* __restrict__ C,
    int N, int K,
    long aBS, int aRS, const int* __restrict__ aidx,
    long cBS, int cPad, int relu)
{
    __shared__ float AsH[16][136];
    __shared__ float BsH[16][136];
    __shared__ float AsL[16][136];
    __shared__ float BsL[16][136];

    const int t    = threadIdx.x;
    const int m0   = blockIdx.y * 128;
    const int n0   = blockIdx.x * 128;
    const int lane = t & 31, warp = t >> 5;
    const int wm   = warp >> 2, wn = warp & 3;
    const int grp  = lane >> 2, qid = lane & 3;

    // --- A staging addressing: thread -> row (t&127), k-quads {t>>7, t>>7+2}
    const int am  = t & 127;
    const int akq = t >> 7;
    long mA = m0 + am;
    const float* Ap;
    if (aidx) {
        Ap = A + (long)aidx[mA] * K;
    } else {
        long bb = mA >> 11, ll = mA & 2047;
        Ap = A + bb * aBS + ll * (long)aRS;
    }

    // --- B staging addressing: thread -> 4 cols (t&31)*4, rows {t>>5, t>>5+8}
    const int bn  = (t & 31) * 4;
    const int bkr = t >> 5;
    const bool bok = (n0 + bn) < N;
    const float* Bph = Bh + (long)bkr * N + n0 + bn;
    const float* Bpl = SPLIT ? (Bl + (long)bkr * N + n0 + bn) : Bh;

    float acc[4][4][4];
#pragma unroll
    for (int i = 0; i < 4; i++)
#pragma unroll
        for (int j = 0; j < 4; j++)
#pragma unroll
            for (int c = 0; c < 4; c++) acc[i][j][c] = 0.f;

    float4 aR0, aR1;
    float4 bh0 = make_float4(0.f,0.f,0.f,0.f), bh1 = bh0, bl0 = bh0, bl1 = bh0;

    // prologue: prefetch tile kt=0
    aR0 = *(const float4*)(Ap + akq * 4);
    aR1 = *(const float4*)(Ap + akq * 4 + 8);
    if (bok) {
        bh0 = *(const float4*)(Bph);
        bh1 = *(const float4*)(Bph + 8 * (long)N);
        if (SPLIT) {
            bl0 = *(const float4*)(Bpl);
            bl1 = *(const float4*)(Bpl + 8 * (long)N);
        }
    }

    for (int kt = 0; kt < K; kt += 16) {
        // ---- store staged regs to smem (A transposed + tf32 rounded/split) ----
        {
            const float av[8] = {aR0.x, aR0.y, aR0.z, aR0.w, aR1.x, aR1.y, aR1.z, aR1.w};
#pragma unroll
            for (int c = 0; c < 8; c++) {
                int kk = (c < 4) ? (akq * 4 + c) : ((akq + 2) * 4 + (c - 4));
                float x = av[c];
                uint32_t hb = f2tf(x);
                AsH[kk][am] = __uint_as_float(hb);
                if (SPLIT)
                    AsL[kk][am] = __uint_as_float(f2tf(x - __uint_as_float(hb)));
            }
            *(float4*)&BsH[bkr][bn]     = bh0;
            *(float4*)&BsH[bkr + 8][bn] = bh1;
            if (SPLIT) {
                *(float4*)&BsL[bkr][bn]     = bl0;
                *(float4*)&BsL[bkr + 8][bn] = bl1;
            }
        }
        __syncthreads();

        // ---- prefetch next tile (overlaps with compute below) ----
        if (kt + 16 < K) {
            aR0 = *(const float4*)(Ap + kt + 16 + akq * 4);
            aR1 = *(const float4*)(Ap + kt + 16 + akq * 4 + 8);
            if (bok) {
                const float* p = Bph + (long)(kt + 16) * N;
                bh0 = *(const float4*)(p);
                bh1 = *(const float4*)(p + 8 * (long)N);
                if (SPLIT) {
                    const float* q = Bpl + (long)(kt + 16) * N;
                    bl0 = *(const float4*)(q);
                    bl1 = *(const float4*)(q + 8 * (long)N);
                }
            }
        }

        // ---- compute 2 k-steps of 8 ----
#pragma unroll
        for (int ks = 0; ks < 2; ks++) {
            const int k0 = ks * 8;
            uint32_t fa[4][4], fb[4][2];
#pragma unroll
            for (int mf = 0; mf < 4; mf++) {
                int mo = wm * 64 + mf * 16 + grp;
                fa[mf][0] = __float_as_uint(AsH[k0 + qid    ][mo    ]);
                fa[mf][1] = __float_as_uint(AsH[k0 + qid    ][mo + 8]);
                fa[mf][2] = __float_as_uint(AsH[k0 + qid + 4][mo    ]);
                fa[mf][3] = __float_as_uint(AsH[k0 + qid + 4][mo + 8]);
            }
#pragma unroll
            for (int nf = 0; nf < 4; nf++) {
                int no = wn * 32 + nf * 8 + grp;
                fb[nf][0] = __float_as_uint(BsH[k0 + qid    ][no]);
                fb[nf][1] = __float_as_uint(BsH[k0 + qid + 4][no]);
            }
#pragma unroll
            for (int mf = 0; mf < 4; mf++)
#pragma unroll
                for (int nf = 0; nf < 4; nf++)
                    mma8(acc[mf][nf], fa[mf], fb[nf]);

            if (SPLIT) {
                uint32_t fbl[4][2];
#pragma unroll
                for (int nf = 0; nf < 4; nf++) {
                    int no = wn * 32 + nf * 8 + grp;
                    fbl[nf][0] = __float_as_uint(BsL[k0 + qid    ][no]);
                    fbl[nf][1] = __float_as_uint(BsL[k0 + qid + 4][no]);
                }
#pragma unroll
                for (int mf = 0; mf < 4; mf++)
#pragma unroll
                    for (int nf = 0; nf < 4; nf++)
                        mma8(acc[mf][nf], fa[mf], fbl[nf]);

                uint32_t fal[4][4];
#pragma unroll
                for (int mf = 0; mf < 4; mf++) {
                    int mo = wm * 64 + mf * 16 + grp;
                    fal[mf][0] = __float_as_uint(AsL[k0 + qid    ][mo    ]);
                    fal[mf][1] = __float_as_uint(AsL[k0 + qid    ][mo + 8]);
                    fal[mf][2] = __float_as_uint(AsL[k0 + qid + 4][mo    ]);
                    fal[mf][3] = __float_as_uint(AsL[k0 + qid + 4][mo + 8]);
                }
#pragma unroll
                for (int mf = 0; mf < 4; mf++)
#pragma unroll
                    for (int nf = 0; nf < 4; nf++)
                        mma8(acc[mf][nf], fal[mf], fb[nf]);
            }
        }
        __syncthreads();
    }

    // ---- epilogue: bias + optional relu, float2 stores ----
    const int nwbase = n0 + wn * 32;
    float bv[4][2];
#pragma unroll
    for (int nf = 0; nf < 4; nf++) {
        int n = nwbase + nf * 8 + qid * 2;
        bv[nf][0] = (n < N) ? bias[n] : 0.f;
        bv[nf][1] = (n + 1 < N) ? bias[n + 1] : 0.f;
    }
#pragma unroll
    for (int mf = 0; mf < 4; mf++) {
#pragma unroll
        for (int half = 0; half < 2; half++) {
            long m  = m0 + wm * 64 + mf * 16 + grp + half * 8;
            long bb = m >> 11, ll = m & 2047;
            float* Cp = C + bb * cBS + (ll + cPad) * (long)N;
#pragma unroll
            for (int nf = 0; nf < 4; nf++) {
                int n = nwbase + nf * 8 + qid * 2;
                if (n < N) {
                    float v0 = acc[mf][nf][half * 2 + 0] + bv[nf][0];
                    float v1 = acc[mf][nf][half * 2 + 1] + bv[nf][1];
                    if (relu) { v0 = fmaxf(v0, 0.f); v1 = fmaxf(v1, 0.f); }
                    *(float2*)(Cp + n) = make_float2(v0, v1);
                }
            }
        }
    }
}

// --------------------------- VQ argmin + loss --------------------------------
__global__ __launch_bounds__(256) void argmin_k(
    const float* __restrict__ S, const float* __restrict__ ZE,
    int* __restrict__ codes, float* __restrict__ codesF,
    float* __restrict__ partials)
{
    int lane = threadIdx.x & 31;
    int wid  = threadIdx.x >> 5;
    int m    = blockIdx.x * 8 + wid;

    const float* Sp = S + (long)m * KCODE;
    float best = 3.4e38f;
    int   bi   = KCODE;
#pragma unroll
    for (int i = 0; i < 16; i++) {
        int c = lane + i * 32;
        float v = Sp[c];
        if (v < best) { best = v; bi = c; }
    }
#pragma unroll
    for (int off = 16; off; off >>= 1) {
        float ob = __shfl_down_sync(0xffffffff, best, off);
        int   oi = __shfl_down_sync(0xffffffff, bi, off);
        if (ob < best || (ob == best && oi < bi)) { best = ob; bi = oi; }
    }

    const float* Zp = ZE + (long)m * DCODE;
    float zn = 0.f;
#pragma unroll
    for (int i = 0; i < 2; i++) {
        float v = Zp[lane + i * 32];
        zn = fmaf(v, v, zn);
    }
#pragma unroll
    for (int off = 16; off; off >>= 1)
        zn += __shfl_down_sync(0xffffffff, zn, off);

    __shared__ float sPart[8];
    if (lane == 0) {
        codes[m] = bi;
        if (codesF) codesF[m] = (float)bi;
        sPart[wid] = zn + best;
    }
    __syncthreads();
    if (threadIdx.x == 0) {
        float s = 0.f;
        for (int i = 0; i < 8; i++) s += sPart[i];
        partials[blockIdx.x] = s;
    }
}

__global__ void loss_k(const float* __restrict__ partials, float* __restrict__ out) {
    __shared__ float sh[256];
    float s = 0.f;
    for (int i = threadIdx.x; i < 4096; i += 256) s += partials[i];
    sh[threadIdx.x] = s;
    __syncthreads();
    for (int off = 128; off; off >>= 1) {
        if (threadIdx.x < off) sh[threadIdx.x] += sh[threadIdx.x + off];
        __syncthreads();
    }
    if (threadIdx.x == 0)
        out[0] = 0.1f * sh[0] / (float)(MROWS * DCODE);
}

// ------------------------------- launch -------------------------------------
static float* symf(const void* s) {
    void* p = nullptr;
    cudaGetSymbolAddress(&p, s);
    return (float*)p;
}

template<bool SPLIT>
static void run_gemm(const float* A, const float* Bh, const float* Bl,
                     const float* bias, float* C, int N, int K,
                     long aBS, int aRS, const int* aidx,
                     long cBS, int cPad, int relu)
{
    dim3 grid((N + 127) / 128, MROWS / 128);
    mma_gemm<SPLIT><<<grid, 256>>>(A, Bh, Bl, bias, C, N, K,
                                   aBS, aRS, aidx, cBS, cPad, relu);
}

extern "C" void kernel_launch(void* const* d_in, const int* in_sizes, int n_in,
                              void* d_out, int out_size)
{
    const int*   x        = (const int*)  d_in[0];
    const float* tokenEmb = (const float*)d_in[1];
    const float* ew1 = (const float*)d_in[2];  const float* eb1 = (const float*)d_in[3];
    const float* ew2 = (const float*)d_in[4];  const float* eb2 = (const float*)d_in[5];
    const float* ew3 = (const float*)d_in[6];  const float* eb3 = (const float*)d_in[7];
    const float* cb  = (const float*)d_in[8];
    const float* dw1 = (const float*)d_in[9];  const float* db1 = (const float*)d_in[10];
    const float* dw2 = (const float*)d_in[11]; const float* db2 = (const float*)d_in[12];
    const float* dw3 = (const float*)d_in[13]; const float* db3 = (const float*)d_in[14];
    const float* outW = (const float*)d_in[15];
    const float* outB = (const float*)d_in[16];

    float* out = (float*)d_out;

    float* P0  = symf(g_P0);   float* H1  = symf(g_H1);
    float* H2  = symf(g_H2);   float* ZE  = symf(g_ZE);
    float* S   = symf(g_S);    int*   CODES = (int*)symf(g_CODES);
    float* HD1 = symf(g_HD1);  float* HD2 = symf(g_HD2);
    float* HD3 = symf(g_HD3);  float* PART = symf(g_PART);
    float* W1h = symf(g_W1h);  float* W1l = symf(g_W1l);
    float* W2h = symf(g_W2h);  float* W2l = symf(g_W2l);
    float* W3h = symf(g_W3h);  float* W3l = symf(g_W3l);
    float* CBh = symf(g_CBh);  float* CBl = symf(g_CBl);
    float* CNRM = symf(g_CNRM);
    float* DW1h = symf(g_DW1h); float* DW2h = symf(g_DW2h);
    float* DW3h = symf(g_DW3h); float* OWh  = symf(g_OWh);

    // ---- weight prepack (tf32 hi/lo for encoder+VQ, hi-only for decoder) ----
    pack_k3<<<(HID * EMB * 3 + 255) / 256, 256>>>(ew1, W1h, W1l, HID, EMB);
    pack_k3<<<(HID * HID * 3 + 255) / 256, 256>>>(ew2, W2h, W2l, HID, HID);
    pack_k1<<<(DCODE * HID + 255) / 256, 256>>>(ew3, W3h, W3l, DCODE, HID);
    pack_cb<<<2, 256>>>(cb, CBh, CBl, CNRM);
    pack_k1<<<(HID * DCODE + 255) / 256, 256>>>(dw1, DW1h, nullptr, HID, DCODE);
    pack_k3<<<(HID * HID * 3 + 255) / 256, 256>>>(dw2, DW2h, nullptr, HID, HID);
    pack_k1<<<(EMB * HID + 255) / 256, 256>>>(dw3, DW3h, nullptr, EMB, HID);
    pack_k1<<<(VOCAB * EMB + 255) / 256, 256>>>(outW, OWh, nullptr, VOCAB, EMB);

    // ---- embedding (with pad rows); zero pad rows of padded HID buffers ----
    embed_k<<<(BATCH * LPAD * EMB + 255) / 256, 256>>>(x, tokenEmb, P0);
    zeropad_k<<<(BATCH * 2 * HID * 2 + 255) / 256, 256>>>(H1, symf(g_HD1));

    // ---- encoder (3xTF32 split: fp32-equivalent, keeps VQ codes exact) ----
    run_gemm<true>(P0, W1h, W1l, eb1, H1, HID, 3 * EMB,
                   (long)LPAD * EMB, EMB, nullptr, (long)LPAD * HID, 1, 1);
    run_gemm<true>(H1, W2h, W2l, eb2, H2, HID, 3 * HID,
                   (long)LPAD * HID, HID, nullptr, (long)SEQL * HID, 0, 1);
    run_gemm<true>(H2, W3h, W3l, eb3, ZE, DCODE, HID,
                   (long)SEQL * HID, HID, nullptr, (long)SEQL * DCODE, 0, 0);

    // ---- VQ scores (-2 z.c + |c|^2), split for accuracy; then argmin ----
    run_gemm<true>(ZE, CBh, CBl, CNRM, S, KCODE, DCODE,
                   (long)SEQL * DCODE, DCODE, nullptr, (long)SEQL * KCODE, 0, 0);

    const long LOGN = (long)MROWS * VOCAB;
    bool full_out = ((long)out_size >= LOGN + 1 + MROWS);
    float* codesF = full_out ? (out + LOGN + 1) : nullptr;
    argmin_k<<<MROWS / 8, 256>>>(S, ZE, CODES, codesF, PART);
    if (full_out) loss_k<<<1, 256>>>(PART, out + LOGN);

    // ---- decoder (1xTF32; z_q gathered from raw codebook via CODES) ----
    run_gemm<false>(cb, DW1h, nullptr, db1, HD1, HID, DCODE,
                    0, 0, CODES, (long)LPAD * HID, 1, 1);
    run_gemm<false>(HD1, DW2h, nullptr, db2, HD2, HID, 3 * HID,
                    (long)LPAD * HID, HID, nullptr, (long)SEQL * HID, 0, 1);
    run_gemm<false>(HD2, DW3h, nullptr, db3, HD3, EMB, HID,
                    (long)SEQL * HID, HID, nullptr, (long)SEQL * EMB, 0, 1);

    // ---- vocab projection straight into d_out ----
    run_gemm<false>(HD3, OWh, nullptr, outB, out, VOCAB, EMB,
                    (long)SEQL * EMB, EMB, nullptr, (long)SEQL * VOCAB, 0, 0);
}

// round 8
// speedup vs baseline: 2.0957x; 1.0726x over previous
#include <cuda_runtime.h>
#include <cuda_bf16.h>
#include <cstdint>

// ---------------------------------------------------------------------------
// VQVAE forward on GB300, round 7: tf32 mma.sync GEMMs, double-buffered smem.
//   Encoder convs + VQ scores: 3xTF32 split (fp32-equivalent; VQ codes exact).
//   Decoder convs + vocab:     1xTF32.
//   dec-conv1 replaced by 512-row table GEMM + gather (input = codebook rows).
// Shapes: B=16 L=2048 E=128 H=256 D=64 Kc=512 V=4096, M = B*L = 32768.
// Output: [logits (M*V)] [loss (1)] [codes (M)] as float32.
// ---------------------------------------------------------------------------

#define BATCH 16
#define SEQL  2048
#define LPAD  2050
#define EMB   128
#define HID   256
#define DCODE 64
#define KCODE 512
#define VOCAB 4096
#define MROWS (BATCH * SEQL)   // 32768

// ---------------- scratch (device globals) ----------------------------------
__device__ float g_P0 [BATCH * LPAD * EMB];
__device__ float g_H1 [BATCH * LPAD * HID];
__device__ float g_H2 [BATCH * SEQL * HID];
__device__ float g_ZE [BATCH * SEQL * DCODE];
__device__ float g_S  [MROWS * KCODE];
__device__ int   g_CODES[MROWS];
__device__ float g_T  [KCODE * HID];          // relu(cb @ DW1 + db1) table
__device__ float g_HD1[BATCH * LPAD * HID];
__device__ float g_HD2[BATCH * SEQL * HID];
__device__ float g_HD3[BATCH * SEQL * EMB];
__device__ float g_PART[4096];

// packed weights, tf32 hi (+lo for the split path)
__device__ float g_W1h[3 * EMB * HID],  g_W1l[3 * EMB * HID];
__device__ float g_W2h[3 * HID * HID],  g_W2l[3 * HID * HID];
__device__ float g_W3h[HID * DCODE],    g_W3l[HID * DCODE];
__device__ float g_CBh[DCODE * KCODE],  g_CBl[DCODE * KCODE];
__device__ float g_CNRM[KCODE];
__device__ float g_DW1h[DCODE * HID];
__device__ float g_DW2h[3 * HID * HID];
__device__ float g_DW3h[HID * EMB];
__device__ float g_OWh [EMB * VOCAB];

// ------------------------------ helpers -------------------------------------
__device__ __forceinline__ uint32_t f2tf(float v) {
    uint32_t r;
    asm("cvt.rna.tf32.f32 %0, %1;" : "=r"(r) : "f"(v));
    return r;
}

__device__ __forceinline__ void mma8(float* c, const uint32_t* a, const uint32_t* b) {
    asm volatile(
        "mma.sync.aligned.m16n8k8.row.col.f32.tf32.tf32.f32 "
        "{%0,%1,%2,%3}, {%4,%5,%6,%7}, {%8,%9}, {%0,%1,%2,%3};\n"
        : "+f"(c[0]), "+f"(c[1]), "+f"(c[2]), "+f"(c[3])
        : "r"(a[0]), "r"(a[1]), "r"(a[2]), "r"(a[3]), "r"(b[0]), "r"(b[1]));
}

// ---------------------------- weight prepack --------------------------------
__global__ void pack_k3(const float* __restrict__ w, float* __restrict__ hi,
                        float* __restrict__ lo, int Cout, int Cin) {
    int i = blockIdx.x * blockDim.x + threadIdx.x;
    int tot = Cout * Cin * 3;
    if (i >= tot) return;
    int j = i % 3;
    int e = (i / 3) % Cin;
    int h = i / (3 * Cin);
    int dst = (j * Cin + e) * Cout + h;
    float v = w[i];
    uint32_t hb = f2tf(v);
    hi[dst] = __uint_as_float(hb);
    if (lo) lo[dst] = __uint_as_float(f2tf(v - __uint_as_float(hb)));
}

__global__ void pack_k1(const float* __restrict__ w, float* __restrict__ hi,
                        float* __restrict__ lo, int Cout, int Cin) {
    int i = blockIdx.x * blockDim.x + threadIdx.x;
    if (i >= Cout * Cin) return;
    int e = i % Cin;
    int h = i / Cin;
    int dst = e * Cout + h;
    float v = w[i];
    uint32_t hb = f2tf(v);
    hi[dst] = __uint_as_float(hb);
    if (lo) lo[dst] = __uint_as_float(f2tf(v - __uint_as_float(hb)));
}

// codebook -> B = -2*cb^T (tf32 hi/lo), bias = ||c||^2 exact. Warp per code.
__global__ void pack_cb(const float* __restrict__ cb, float* __restrict__ hi,
                        float* __restrict__ lo, float* __restrict__ cnrm) {
    int k    = blockIdx.x * 8 + (threadIdx.x >> 5);
    int lane = threadIdx.x & 31;
    float s = 0.f;
#pragma unroll
    for (int h = 0; h < 2; h++) {
        int d = lane + h * 32;
        float v = cb[k * DCODE + d];
        float b = -2.0f * v;
        uint32_t hb = f2tf(b);
        hi[d * KCODE + k] = __uint_as_float(hb);
        lo[d * KCODE + k] = __uint_as_float(f2tf(b - __uint_as_float(hb)));
        s = fmaf(v, v, s);
    }
#pragma unroll
    for (int off = 16; off; off >>= 1)
        s += __shfl_down_sync(0xffffffff, s, off);
    if (lane == 0) cnrm[k] = s;
}

// ---------------------------- embedding + pads ------------------------------
__global__ void embed_k(const int* __restrict__ x, const float* __restrict__ emb,
                        float* __restrict__ P0) {
    int i = blockIdx.x * blockDim.x + threadIdx.x;
    const int tot = BATCH * LPAD * EMB;
    if (i >= tot) return;
    int e  = i % EMB;
    int r  = i / EMB;
    int rr = r % LPAD;
    int b  = r / LPAD;
    float v = 0.f;
    if (rr >= 1 && rr <= SEQL)
        v = emb[(long)x[b * SEQL + rr - 1] * EMB + e];
    P0[i] = v;
}

__global__ void zeropad_k(float* __restrict__ H1, float* __restrict__ HD1) {
    int i = blockIdx.x * blockDim.x + threadIdx.x;
    const int per = BATCH * 2 * HID;
    if (i >= per * 2) return;
    float* buf = (i < per) ? H1 : HD1;
    int j = i % per;
    int c = j % HID;
    int w = j / HID;
    int b = w >> 1;
    int row = (w & 1) ? (LPAD - 1) : 0;
    buf[((long)b * LPAD + row) * HID + c] = 0.f;
}

// gather: HD1 padded row (l+1) of batch b  <-  T[codes[m]]   (float4 lanes)
__global__ void gather_k(const float* __restrict__ T, const int* __restrict__ codes,
                         float* __restrict__ HD1) {
    int i   = blockIdx.x * blockDim.x + threadIdx.x;   // < MROWS*64
    int row = i >> 6;
    int c4  = i & 63;
    int code = __ldg(&codes[row]);
    long bb = row >> 11, ll = row & 2047;
    float4 v = ((const float4*)(T + (long)code * HID))[c4];
    ((float4*)(HD1 + (bb * LPAD + ll + 1) * HID))[c4] = v;
}

// ------------------- 3xTF32 split GEMM (BK=8, 2-stage) -----------------------
// C = act(A*B + bias). Tile 128x128x8, 8 warps (2x4), warp tile 64x32.
__global__ __launch_bounds__(256) void gemm_split_k(
    const float* __restrict__ A,
    const float* __restrict__ Bh, const float* __restrict__ Bl,
    const float* __restrict__ bias, float* __restrict__ C,
    int N, int K, long aBS, int aRS, long cBS, int cPad, int relu)
{
    __shared__ float AsH[2][8][136];
    __shared__ float AsL[2][8][136];
    __shared__ float BsH[2][8][136];
    __shared__ float BsL[2][8][136];

    const int t    = threadIdx.x;
    const int m0   = blockIdx.y * 128;
    const int n0   = blockIdx.x * 128;
    const int lane = t & 31, warp = t >> 5;
    const int wm   = warp >> 2, wn = warp & 3;
    const int grp  = lane >> 2, qid = lane & 3;

    // A staging: row am = t&127, k-quad akq = t>>7 (k offset 4*akq)
    const int am  = t & 127;
    const int akq = t >> 7;
    long mA = m0 + am;
    long bbA = mA >> 11, llA = mA & 2047;
    const float* Ap = A + bbA * aBS + llA * (long)aRS + akq * 4;

    // B staging: rows bkr = t>>5 (0..7), cols (t&31)*4
    const int bn  = (t & 31) * 4;
    const int bkr = t >> 5;
    const bool bok = (n0 + bn) < N;
    const float* Bph = Bh + (long)bkr * N + n0 + bn;
    const float* Bpl = Bl + (long)bkr * N + n0 + bn;

    float acc[4][4][4];
#pragma unroll
    for (int i = 0; i < 4; i++)
#pragma unroll
        for (int j = 0; j < 4; j++)
#pragma unroll
            for (int c = 0; c < 4; c++) acc[i][j][c] = 0.f;

    const float4 fz = make_float4(0.f, 0.f, 0.f, 0.f);

    // prologue: stage tile 0
    {
        float4 aV = *(const float4*)(Ap);
        float4 bhV = bok ? *(const float4*)(Bph) : fz;
        float4 blV = bok ? *(const float4*)(Bpl) : fz;
        const float av[4] = {aV.x, aV.y, aV.z, aV.w};
#pragma unroll
        for (int c = 0; c < 4; c++) {
            uint32_t hb = f2tf(av[c]);
            AsH[0][akq * 4 + c][am] = __uint_as_float(hb);
            AsL[0][akq * 4 + c][am] = __uint_as_float(f2tf(av[c] - __uint_as_float(hb)));
        }
        *(float4*)&BsH[0][bkr][bn] = bhV;
        *(float4*)&BsL[0][bkr][bn] = blV;
    }
    __syncthreads();

    int cur = 0;
    for (int kt = 0; kt < K; kt += 8) {
        const bool more = (kt + 8) < K;
        float4 aN = fz, bhN = fz, blN = fz;
        if (more) {
            aN = *(const float4*)(Ap + kt + 8);
            if (bok) {
                bhN = *(const float4*)(Bph + (long)(kt + 8) * N);
                blN = *(const float4*)(Bpl + (long)(kt + 8) * N);
            }
        }

        // ---- compute k-step of 8 from stage cur ----
        uint32_t fa[4][4], fb[4][2];
#pragma unroll
        for (int mf = 0; mf < 4; mf++) {
            int mo = wm * 64 + mf * 16 + grp;
            fa[mf][0] = __float_as_uint(AsH[cur][qid    ][mo    ]);
            fa[mf][1] = __float_as_uint(AsH[cur][qid    ][mo + 8]);
            fa[mf][2] = __float_as_uint(AsH[cur][qid + 4][mo    ]);
            fa[mf][3] = __float_as_uint(AsH[cur][qid + 4][mo + 8]);
        }
#pragma unroll
        for (int nf = 0; nf < 4; nf++) {
            int no = wn * 32 + nf * 8 + grp;
            fb[nf][0] = __float_as_uint(BsH[cur][qid    ][no]);
            fb[nf][1] = __float_as_uint(BsH[cur][qid + 4][no]);
        }
#pragma unroll
        for (int mf = 0; mf < 4; mf++)
#pragma unroll
            for (int nf = 0; nf < 4; nf++)
                mma8(acc[mf][nf], fa[mf], fb[nf]);

        uint32_t fbl[4][2];
#pragma unroll
        for (int nf = 0; nf < 4; nf++) {
            int no = wn * 32 + nf * 8 + grp;
            fbl[nf][0] = __float_as_uint(BsL[cur][qid    ][no]);
            fbl[nf][1] = __float_as_uint(BsL[cur][qid + 4][no]);
        }
#pragma unroll
        for (int mf = 0; mf < 4; mf++)
#pragma unroll
            for (int nf = 0; nf < 4; nf++)
                mma8(acc[mf][nf], fa[mf], fbl[nf]);

        uint32_t fal[4][4];
#pragma unroll
        for (int mf = 0; mf < 4; mf++) {
            int mo = wm * 64 + mf * 16 + grp;
            fal[mf][0] = __float_as_uint(AsL[cur][qid    ][mo    ]);
            fal[mf][1] = __float_as_uint(AsL[cur][qid    ][mo + 8]);
            fal[mf][2] = __float_as_uint(AsL[cur][qid + 4][mo    ]);
            fal[mf][3] = __float_as_uint(AsL[cur][qid + 4][mo + 8]);
        }
#pragma unroll
        for (int mf = 0; mf < 4; mf++)
#pragma unroll
            for (int nf = 0; nf < 4; nf++)
                mma8(acc[mf][nf], fal[mf], fb[nf]);

        // ---- stage next tile into the other buffer ----
        if (more) {
            const int nxt = cur ^ 1;
            const float av[4] = {aN.x, aN.y, aN.z, aN.w};
#pragma unroll
            for (int c = 0; c < 4; c++) {
                uint32_t hb = f2tf(av[c]);
                AsH[nxt][akq * 4 + c][am] = __uint_as_float(hb);
                AsL[nxt][akq * 4 + c][am] = __uint_as_float(f2tf(av[c] - __uint_as_float(hb)));
            }
            *(float4*)&BsH[nxt][bkr][bn] = bhN;
            *(float4*)&BsL[nxt][bkr][bn] = blN;
        }
        __syncthreads();
        cur ^= 1;
    }

    // ---- epilogue ----
    const int nwbase = n0 + wn * 32;
    float bv[4][2];
#pragma unroll
    for (int nf = 0; nf < 4; nf++) {
        int n = nwbase + nf * 8 + qid * 2;
        bv[nf][0] = (n < N) ? bias[n] : 0.f;
        bv[nf][1] = (n + 1 < N) ? bias[n + 1] : 0.f;
    }
#pragma unroll
    for (int mf = 0; mf < 4; mf++) {
#pragma unroll
        for (int half = 0; half < 2; half++) {
            long m  = m0 + wm * 64 + mf * 16 + grp + half * 8;
            long bb = m >> 11, ll = m & 2047;
            float* Cp = C + bb * cBS + (ll + cPad) * (long)N;
#pragma unroll
            for (int nf = 0; nf < 4; nf++) {
                int n = nwbase + nf * 8 + qid * 2;
                if (n < N) {
                    float v0 = acc[mf][nf][half * 2 + 0] + bv[nf][0];
                    float v1 = acc[mf][nf][half * 2 + 1] + bv[nf][1];
                    if (relu) { v0 = fmaxf(v0, 0.f); v1 = fmaxf(v1, 0.f); }
                    *(float2*)(Cp + n) = make_float2(v0, v1);
                }
            }
        }
    }
}

// ------------------- 1xTF32 GEMM (BK=16, 2-stage) ----------------------------
__global__ __launch_bounds__(256, 2) void gemm_fast_k(
    const float* __restrict__ A, const float* __restrict__ Bh,
    const float* __restrict__ bias, float* __restrict__ C,
    int N, int K, long aBS, int aRS, long cBS, int cPad, int relu)
{
    __shared__ float AsH[2][16][136];
    __shared__ float BsH[2][16][136];

    const int t    = threadIdx.x;
    const int m0   = blockIdx.y * 128;
    const int n0   = blockIdx.x * 128;
    const int lane = t & 31, warp = t >> 5;
    const int wm   = warp >> 2, wn = warp & 3;
    const int grp  = lane >> 2, qid = lane & 3;

    const int am  = t & 127;
    const int akq = t >> 7;       // thread covers k {4akq..4akq+3, 4akq+8..4akq+11}
    long mA = m0 + am;
    long bbA = mA >> 11, llA = mA & 2047;
    const float* Ap = A + bbA * aBS + llA * (long)aRS;

    const int bn  = (t & 31) * 4;
    const int bkr = t >> 5;       // rows {bkr, bkr+8}
    const bool bok = (n0 + bn) < N;
    const float* Bph = Bh + (long)bkr * N + n0 + bn;

    float acc[4][4][4];
#pragma unroll
    for (int i = 0; i < 4; i++)
#pragma unroll
        for (int j = 0; j < 4; j++)
#pragma unroll
            for (int c = 0; c < 4; c++) acc[i][j][c] = 0.f;

    const float4 fz = make_float4(0.f, 0.f, 0.f, 0.f);

    // prologue: stage tile 0
    {
        float4 a0 = *(const float4*)(Ap + akq * 4);
        float4 a1 = *(const float4*)(Ap + akq * 4 + 8);
        float4 b0 = bok ? *(const float4*)(Bph) : fz;
        float4 b1 = bok ? *(const float4*)(Bph + 8 * (long)N) : fz;
        const float av[8] = {a0.x, a0.y, a0.z, a0.w, a1.x, a1.y, a1.z, a1.w};
#pragma unroll
        for (int c = 0; c < 8; c++) {
            int kk = (c < 4) ? (akq * 4 + c) : (akq * 4 + 4 + c);  // +8 offset for c>=4
            AsH[0][kk][am] = __uint_as_float(f2tf(av[c]));
        }
        *(float4*)&BsH[0][bkr][bn]     = b0;
        *(float4*)&BsH[0][bkr + 8][bn] = b1;
    }
    __syncthreads();

    int cur = 0;
    for (int kt = 0; kt < K; kt += 16) {
        const bool more = (kt + 16) < K;
        float4 a0 = fz, a1 = fz, b0 = fz, b1 = fz;
        if (more) {
            a0 = *(const float4*)(Ap + kt + 16 + akq * 4);
            a1 = *(const float4*)(Ap + kt + 16 + akq * 4 + 8);
            if (bok) {
                const float* p = Bph + (long)(kt + 16) * N;
                b0 = *(const float4*)(p);
                b1 = *(const float4*)(p + 8 * (long)N);
            }
        }

#pragma unroll
        for (int ks = 0; ks < 2; ks++) {
            const int k0 = ks * 8;
            uint32_t fa[4][4], fb[4][2];
#pragma unroll
            for (int mf = 0; mf < 4; mf++) {
                int mo = wm * 64 + mf * 16 + grp;
                fa[mf][0] = __float_as_uint(AsH[cur][k0 + qid    ][mo    ]);
                fa[mf][1] = __float_as_uint(AsH[cur][k0 + qid    ][mo + 8]);
                fa[mf][2] = __float_as_uint(AsH[cur][k0 + qid + 4][mo    ]);
                fa[mf][3] = __float_as_uint(AsH[cur][k0 + qid + 4][mo + 8]);
            }
#pragma unroll
            for (int nf = 0; nf < 4; nf++) {
                int no = wn * 32 + nf * 8 + grp;
                fb[nf][0] = __float_as_uint(BsH[cur][k0 + qid    ][no]);
                fb[nf][1] = __float_as_uint(BsH[cur][k0 + qid + 4][no]);
            }
#pragma unroll
            for (int mf = 0; mf < 4; mf++)
#pragma unroll
                for (int nf = 0; nf < 4; nf++)
                    mma8(acc[mf][nf], fa[mf], fb[nf]);
        }

        if (more) {
            const int nxt = cur ^ 1;
            const float av[8] = {a0.x, a0.y, a0.z, a0.w, a1.x, a1.y, a1.z, a1.w};
#pragma unroll
            for (int c = 0; c < 8; c++) {
                int kk = (c < 4) ? (akq * 4 + c) : (akq * 4 + 4 + c);
                AsH[nxt][kk][am] = __uint_as_float(f2tf(av[c]));
            }
            *(float4*)&BsH[nxt][bkr][bn]     = b0;
            *(float4*)&BsH[nxt][bkr + 8][bn] = b1;
        }
        __syncthreads();
        cur ^= 1;
    }

    // ---- epilogue ----
    const int nwbase = n0 + wn * 32;
    float bv[4][2];
#pragma unroll
    for (int nf = 0; nf < 4; nf++) {
        int n = nwbase + nf * 8 + qid * 2;
        bv[nf][0] = (n < N) ? bias[n] : 0.f;
        bv[nf][1] = (n + 1 < N) ? bias[n + 1] : 0.f;
    }
#pragma unroll
    for (int mf = 0; mf < 4; mf++) {
#pragma unroll
        for (int half = 0; half < 2; half++) {
            long m  = m0 + wm * 64 + mf * 16 + grp + half * 8;
            long bb = m >> 11, ll = m & 2047;
            float* Cp = C + bb * cBS + (ll + cPad) * (long)N;
#pragma unroll
            for (int nf = 0; nf < 4; nf++) {
                int n = nwbase + nf * 8 + qid * 2;
                if (n < N) {
                    float v0 = acc[mf][nf][half * 2 + 0] + bv[nf][0];
                    float v1 = acc[mf][nf][half * 2 + 1] + bv[nf][1];
                    if (relu) { v0 = fmaxf(v0, 0.f); v1 = fmaxf(v1, 0.f); }
                    *(float2*)(Cp + n) = make_float2(v0, v1);
                }
            }
        }
    }
}

// --------------------------- VQ argmin + loss --------------------------------
__global__ __launch_bounds__(256) void argmin_k(
    const float* __restrict__ S, const float* __restrict__ ZE,
    int* __restrict__ codes, float* __restrict__ codesF,
    float* __restrict__ partials)
{
    int lane = threadIdx.x & 31;
    int wid  = threadIdx.x >> 5;
    int m    = blockIdx.x * 8 + wid;

    const float* Sp = S + (long)m * KCODE;
    float best = 3.4e38f;
    int   bi   = KCODE;
#pragma unroll
    for (int i = 0; i < 16; i++) {
        int c = lane + i * 32;
        float v = Sp[c];
        if (v < best) { best = v; bi = c; }
    }
#pragma unroll
    for (int off = 16; off; off >>= 1) {
        float ob = __shfl_down_sync(0xffffffff, best, off);
        int   oi = __shfl_down_sync(0xffffffff, bi, off);
        if (ob < best || (ob == best && oi < bi)) { best = ob; bi = oi; }
    }

    const float* Zp = ZE + (long)m * DCODE;
    float zn = 0.f;
#pragma unroll
    for (int i = 0; i < 2; i++) {
        float v = Zp[lane + i * 32];
        zn = fmaf(v, v, zn);
    }
#pragma unroll
    for (int off = 16; off; off >>= 1)
        zn += __shfl_down_sync(0xffffffff, zn, off);

    __shared__ float sPart[8];
    if (lane == 0) {
        codes[m] = bi;
        if (codesF) codesF[m] = (float)bi;
        sPart[wid] = zn + best;
    }
    __syncthreads();
    if (threadIdx.x == 0) {
        float s = 0.f;
        for (int i = 0; i < 8; i++) s += sPart[i];
        partials[blockIdx.x] = s;
    }
}

__global__ void loss_k(const float* __restrict__ partials, float* __restrict__ out) {
    __shared__ float sh[256];
    float s = 0.f;
    for (int i = threadIdx.x; i < 4096; i += 256) s += partials[i];
    sh[threadIdx.x] = s;
    __syncthreads();
    for (int off = 128; off; off >>= 1) {
        if (threadIdx.x < off) sh[threadIdx.x] += sh[threadIdx.x + off];
        __syncthreads();
    }
    if (threadIdx.x == 0)
        out[0] = 0.1f * sh[0] / (float)(MROWS * DCODE);
}

// ------------------------------- launch -------------------------------------
static float* symf(const void* s) {
    void* p = nullptr;
    cudaGetSymbolAddress(&p, s);
    return (float*)p;
}

static void run_split(const float* A, const float* Bh, const float* Bl,
                      const float* bias, float* C, int N, int K,
                      long aBS, int aRS, long cBS, int cPad, int relu)
{
    dim3 grid((N + 127) / 128, MROWS / 128);
    gemm_split_k<<<grid, 256>>>(A, Bh, Bl, bias, C, N, K, aBS, aRS, cBS, cPad, relu);
}

static void run_fast(const float* A, const float* Bh, const float* bias, float* C,
                     int M, int N, int K, long aBS, int aRS,
                     long cBS, int cPad, int relu)
{
    dim3 grid((N + 127) / 128, M / 128);
    gemm_fast_k<<<grid, 256>>>(A, Bh, bias, C, N, K, aBS, aRS, cBS, cPad, relu);
}

extern "C" void kernel_launch(void* const* d_in, const int* in_sizes, int n_in,
                              void* d_out, int out_size)
{
    const int*   x        = (const int*)  d_in[0];
    const float* tokenEmb = (const float*)d_in[1];
    const float* ew1 = (const float*)d_in[2];  const float* eb1 = (const float*)d_in[3];
    const float* ew2 = (const float*)d_in[4];  const float* eb2 = (const float*)d_in[5];
    const float* ew3 = (const float*)d_in[6];  const float* eb3 = (const float*)d_in[7];
    const float* cb  = (const float*)d_in[8];
    const float* dw1 = (const float*)d_in[9];  const float* db1 = (const float*)d_in[10];
    const float* dw2 = (const float*)d_in[11]; const float* db2 = (const float*)d_in[12];
    const float* dw3 = (const float*)d_in[13]; const float* db3 = (const float*)d_in[14];
    const float* outW = (const float*)d_in[15];
    const float* outB = (const float*)d_in[16];

    float* out = (float*)d_out;

    float* P0  = symf(g_P0);   float* H1  = symf(g_H1);
    float* H2  = symf(g_H2);   float* ZE  = symf(g_ZE);
    float* S   = symf(g_S);    int*   CODES = (int*)symf(g_CODES);
    float* T   = symf(g_T);
    float* HD1 = symf(g_HD1);  float* HD2 = symf(g_HD2);
    float* HD3 = symf(g_HD3);  float* PART = symf(g_PART);
    float* W1h = symf(g_W1h);  float* W1l = symf(g_W1l);
    float* W2h = symf(g_W2h);  float* W2l = symf(g_W2l);
    float* W3h = symf(g_W3h);  float* W3l = symf(g_W3l);
    float* CBh = symf(g_CBh);  float* CBl = symf(g_CBl);
    float* CNRM = symf(g_CNRM);
    float* DW1h = symf(g_DW1h); float* DW2h = symf(g_DW2h);
    float* DW3h = symf(g_DW3h); float* OWh  = symf(g_OWh);

    // ---- weight prepack ----
    pack_k3<<<(HID * EMB * 3 + 255) / 256, 256>>>(ew1, W1h, W1l, HID, EMB);
    pack_k3<<<(HID * HID * 3 + 255) / 256, 256>>>(ew2, W2h, W2l, HID, HID);
    pack_k1<<<(DCODE * HID + 255) / 256, 256>>>(ew3, W3h, W3l, DCODE, HID);
    pack_cb<<<KCODE / 8, 256>>>(cb, CBh, CBl, CNRM);
    pack_k1<<<(HID * DCODE + 255) / 256, 256>>>(dw1, DW1h, nullptr, HID, DCODE);
    pack_k3<<<(HID * HID * 3 + 255) / 256, 256>>>(dw2, DW2h, nullptr, HID, HID);
    pack_k1<<<(EMB * HID + 255) / 256, 256>>>(dw3, DW3h, nullptr, EMB, HID);
    pack_k1<<<(VOCAB * EMB + 255) / 256, 256>>>(outW, OWh, nullptr, VOCAB, EMB);

    // ---- embedding; zero pad rows of padded HID buffers ----
    embed_k<<<(BATCH * LPAD * EMB + 255) / 256, 256>>>(x, tokenEmb, P0);
    zeropad_k<<<(BATCH * 2 * HID * 2 + 255) / 256, 256>>>(H1, HD1);

    // ---- dec-conv1 table: T = relu(cb @ DW1 + db1), 512x256 (codes-independent)
    run_fast(cb, DW1h, db1, T, KCODE, HID, DCODE, 0, DCODE, 0, 0, 1);

    // ---- encoder (3xTF32 split: fp32-equivalent, keeps VQ codes exact) ----
    run_split(P0, W1h, W1l, eb1, H1, HID, 3 * EMB,
              (long)LPAD * EMB, EMB, (long)LPAD * HID, 1, 1);
    run_split(H1, W2h, W2l, eb2, H2, HID, 3 * HID,
              (long)LPAD * HID, HID, (long)SEQL * HID, 0, 1);
    run_split(H2, W3h, W3l, eb3, ZE, DCODE, HID,
              (long)SEQL * HID, HID, (long)SEQL * DCODE, 0, 0);

    // ---- VQ scores (-2 z.c + |c|^2) + argmin + loss ----
    run_split(ZE, CBh, CBl, CNRM, S, KCODE, DCODE,
              (long)SEQL * DCODE, DCODE, (long)SEQL * KCODE, 0, 0);

    const long LOGN = (long)MROWS * VOCAB;
    bool full_out = ((long)out_size >= LOGN + 1 + MROWS);
    float* codesF = full_out ? (out + LOGN + 1) : nullptr;
    argmin_k<<<MROWS / 8, 256>>>(S, ZE, CODES, codesF, PART);
    if (full_out) loss_k<<<1, 256>>>(PART, out + LOGN);

    // ---- decoder: gather dec-conv1 rows from table, then GEMMs (1xTF32) ----
    gather_k<<<(MROWS * (HID / 4)) / 256, 256>>>(T, CODES, HD1);
    run_fast(HD1, DW2h, db2, HD2, MROWS, HID, 3 * HID,
             (long)LPAD * HID, HID, (long)SEQL * HID, 0, 1);
    run_fast(HD2, DW3h, db3, HD3, MROWS, EMB, HID,
             (long)SEQL * HID, HID, (long)SEQL * EMB, 0, 1);

    // ---- vocab projection straight into d_out ----
    run_fast(HD3, OWh, outB, out, MROWS, VOCAB, EMB,
             (long)SEQL * EMB, EMB, (long)SEQL * VOCAB, 0, 0);
}

// round 13
// speedup vs baseline: 2.7949x; 1.3336x over previous
#include <cuda_runtime.h>
#include <cuda_fp16.h>
#include <cstdint>

// ---------------------------------------------------------------------------
// VQVAE forward on GB300, round 10 (= round 9 resubmit after infra failure):
// fp16 mma.m16n8k16 GEMMs (2x FLOP/instr vs tf32 k8, which was
// issue-rate-bound at ~109 TF/s).
//   Encoder convs + VQ scores: fp16 hi/lo split (lo scaled 2^11), 3 mma/k16,
//     error ~2^-21 (fp32-class) -> VQ codes exact.
//   Decoder convs + vocab:     plain fp16 (same 10-bit mantissa as tf32).
// Shapes: B=16 L=2048 E=128 H=256 D=64 Kc=512 V=4096, M = B*L = 32768.
// Output: [logits (M*V)] [loss (1)] [codes (M)] as float32.
// ---------------------------------------------------------------------------

#define BATCH 16
#define SEQL  2048
#define LPAD  2050
#define EMB   128
#define HID   256
#define DCODE 64
#define KCODE 512
#define VOCAB 4096
#define MROWS (BATCH * SEQL)   // 32768

#define INV2048 4.8828125e-4f

// ---------------- scratch (device globals) ----------------------------------
__device__ float g_P0 [BATCH * LPAD * EMB];
__device__ float g_H1 [BATCH * LPAD * HID];
__device__ float g_H2 [BATCH * SEQL * HID];
__device__ float g_ZE [BATCH * SEQL * DCODE];
__device__ float g_S  [MROWS * KCODE];
__device__ int   g_CODES[MROWS];
__device__ float g_T  [KCODE * HID];          // relu(cb @ DW1 + db1) table
__device__ float g_HD1[BATCH * LPAD * HID];
__device__ float g_HD2[BATCH * SEQL * HID];
__device__ float g_HD3[BATCH * SEQL * EMB];
__device__ float g_PART[4096];

// packed weights, half, [n][k] layout (hi + scaled-lo for the split path)
__device__ __half g_W1h[HID * 3 * EMB],  g_W1l[HID * 3 * EMB];
__device__ __half g_W2h[HID * 3 * HID],  g_W2l[HID * 3 * HID];
__device__ __half g_W3h[DCODE * HID],    g_W3l[DCODE * HID];
__device__ __half g_CBh[KCODE * DCODE],  g_CBl[KCODE * DCODE];
__device__ float  g_CNRM[KCODE];
__device__ __half g_DW1h[HID * DCODE];
__device__ __half g_DW2h[HID * 3 * HID];
__device__ __half g_DW3h[EMB * HID];
__device__ __half g_OWh [VOCAB * EMB];

// ------------------------------ helpers -------------------------------------
__device__ __forceinline__ void mma16(float* c, const uint32_t* a, const uint32_t* b) {
    asm volatile(
        "mma.sync.aligned.m16n8k16.row.col.f32.f16.f16.f32 "
        "{%0,%1,%2,%3}, {%4,%5,%6,%7}, {%8,%9}, {%0,%1,%2,%3};\n"
        : "+f"(c[0]), "+f"(c[1]), "+f"(c[2]), "+f"(c[3])
        : "r"(a[0]), "r"(a[1]), "r"(a[2]), "r"(a[3]), "r"(b[0]), "r"(b[1]));
}

__device__ __forceinline__ uint32_t pack2(float a, float b) {
    __half2 h = __floats2half2_rn(a, b);
    return *(uint32_t*)&h;
}

// ---------------------------- weight prepack --------------------------------
// k3 conv weight (Cout,Cin,3) -> [n=Cout][k=j*Cin+e] half (hi, scaled lo)
__global__ void pack_k3h(const float* __restrict__ w, __half* __restrict__ hi,
                         __half* __restrict__ lo, int Cout, int Cin) {
    int i = blockIdx.x * blockDim.x + threadIdx.x;
    int tot = Cout * Cin * 3;
    if (i >= tot) return;
    int j = i % 3;
    int e = (i / 3) % Cin;
    int h = i / (3 * Cin);
    int dst = h * (3 * Cin) + j * Cin + e;
    float v = w[i];
    __half hh = __float2half_rn(v);
    hi[dst] = hh;
    if (lo) lo[dst] = __float2half_rn((v - __half2float(hh)) * 2048.0f);
}

// k1 / dense weight (Cout,Cin) -> [n][k] = identity layout, elementwise cvt
__global__ void pack_cvt(const float* __restrict__ w, __half* __restrict__ hi,
                         __half* __restrict__ lo, int tot) {
    int i = blockIdx.x * blockDim.x + threadIdx.x;
    if (i >= tot) return;
    float v = w[i];
    __half hh = __float2half_rn(v);
    hi[i] = hh;
    if (lo) lo[i] = __float2half_rn((v - __half2float(hh)) * 2048.0f);
}

// codebook -> W = -2*cb  [n=code][k=d] half hi/lo, bias = ||c||^2 fp32 exact
__global__ void pack_cbh(const float* __restrict__ cb, __half* __restrict__ hi,
                         __half* __restrict__ lo, float* __restrict__ cnrm) {
    int k    = blockIdx.x * 8 + (threadIdx.x >> 5);
    int lane = threadIdx.x & 31;
    float s = 0.f;
#pragma unroll
    for (int h = 0; h < 2; h++) {
        int d = lane + h * 32;
        float v = cb[k * DCODE + d];
        float b = -2.0f * v;
        __half hh = __float2half_rn(b);
        hi[k * DCODE + d] = hh;
        lo[k * DCODE + d] = __float2half_rn((b - __half2float(hh)) * 2048.0f);
        s = fmaf(v, v, s);
    }
#pragma unroll
    for (int off = 16; off; off >>= 1)
        s += __shfl_down_sync(0xffffffff, s, off);
    if (lane == 0) cnrm[k] = s;
}

// ---------------------------- embedding + pads ------------------------------
__global__ void embed_k(const int* __restrict__ x, const float* __restrict__ emb,
                        float* __restrict__ P0) {
    int i = blockIdx.x * blockDim.x + threadIdx.x;
    const int tot = BATCH * LPAD * EMB;
    if (i >= tot) return;
    int e  = i % EMB;
    int r  = i / EMB;
    int rr = r % LPAD;
    int b  = r / LPAD;
    float v = 0.f;
    if (rr >= 1 && rr <= SEQL)
        v = emb[(long)x[b * SEQL + rr - 1] * EMB + e];
    P0[i] = v;
}

__global__ void zeropad_k(float* __restrict__ H1, float* __restrict__ HD1) {
    int i = blockIdx.x * blockDim.x + threadIdx.x;
    const int per = BATCH * 2 * HID;
    if (i >= per * 2) return;
    float* buf = (i < per) ? H1 : HD1;
    int j = i % per;
    int c = j % HID;
    int w = j / HID;
    int b = w >> 1;
    int row = (w & 1) ? (LPAD - 1) : 0;
    buf[((long)b * LPAD + row) * HID + c] = 0.f;
}

// gather: HD1 padded row (l+1) of batch b  <-  T[codes[m]]   (float4 lanes)
__global__ void gather_k(const float* __restrict__ T, const int* __restrict__ codes,
                         float* __restrict__ HD1) {
    int i   = blockIdx.x * blockDim.x + threadIdx.x;   // < MROWS*64
    int row = i >> 6;
    int c4  = i & 63;
    int code = __ldg(&codes[row]);
    long bb = row >> 11, ll = row & 2047;
    float4 v = ((const float4*)(T + (long)code * HID))[c4];
    ((float4*)(HD1 + (bb * LPAD + ll + 1) * HID))[c4] = v;
}

// ------------------- fp16 split GEMM (hi/lo, 3 mma per k16) ------------------
// C = act(A*W^T + bias); A fp32 [m][k] global, W half [n][k] global.
// Tile 128x128x16, 8 warps (2x4), warp tile 64x32.
__global__ __launch_bounds__(256) void gemm16_split_k(
    const float* __restrict__ A,
    const __half* __restrict__ Wh, const __half* __restrict__ Wl,
    const float* __restrict__ bias, float* __restrict__ C,
    int N, int K, long aBS, int aRS, long cBS, int cPad, int relu)
{
    __shared__ uint32_t AsH[2][1024];
    __shared__ uint32_t AsL[2][1024];
    __shared__ uint32_t WsH[2][1024];
    __shared__ uint32_t WsL[2][1024];

    const int t    = threadIdx.x;
    const int m0   = blockIdx.y * 128;
    const int n0   = blockIdx.x * 128;
    const int lane = t & 31, warp = t >> 5;
    const int wm   = warp >> 2, wn = warp & 3;
    const int grp  = lane >> 2, qid = lane & 3;

    // staging: thread -> row t>>1, k-half sh = t&1 (8 halves)
    const int srow = t >> 1;
    const int sh   = t & 1;
    long mA = m0 + srow;
    long bbA = mA >> 11, llA = mA & 2047;
    const float* Ap = A + bbA * aBS + llA * (long)aRS + sh * 8;

    const int nrow = n0 + srow;
    const bool wok = nrow < N;
    const __half* Wph = Wh + (long)nrow * K + sh * 8;
    const __half* Wpl = Wl + (long)nrow * K + sh * 8;

    float accH[4][4][4], accL[4][4][4];
#pragma unroll
    for (int i = 0; i < 4; i++)
#pragma unroll
        for (int j = 0; j < 4; j++)
#pragma unroll
            for (int c = 0; c < 4; c++) { accH[i][j][c] = 0.f; accL[i][j][c] = 0.f; }

    const int sb = srow * 8;
    const int sx = srow & 7;
    const int s0 = sh * 4;
    const uint4 uz = make_uint4(0u, 0u, 0u, 0u);

    // prologue: stage tile 0
    {
        float4 a0 = *(const float4*)(Ap);
        float4 a1 = *(const float4*)(Ap + 4);
        uint4 wh = wok ? *(const uint4*)(Wph) : uz;
        uint4 wl = wok ? *(const uint4*)(Wpl) : uz;
        float av[8] = {a0.x, a0.y, a0.z, a0.w, a1.x, a1.y, a1.z, a1.w};
        float hv[8], lv[8];
#pragma unroll
        for (int c = 0; c < 8; c++) {
            __half hh = __float2half_rn(av[c]);
            hv[c] = __half2float(hh);
            lv[c] = (av[c] - hv[c]) * 2048.0f;
        }
        AsH[0][sb + ((s0+0)^sx)] = pack2(hv[0], hv[1]);
        AsH[0][sb + ((s0+1)^sx)] = pack2(hv[2], hv[3]);
        AsH[0][sb + ((s0+2)^sx)] = pack2(hv[4], hv[5]);
        AsH[0][sb + ((s0+3)^sx)] = pack2(hv[6], hv[7]);
        AsL[0][sb + ((s0+0)^sx)] = pack2(lv[0], lv[1]);
        AsL[0][sb + ((s0+1)^sx)] = pack2(lv[2], lv[3]);
        AsL[0][sb + ((s0+2)^sx)] = pack2(lv[4], lv[5]);
        AsL[0][sb + ((s0+3)^sx)] = pack2(lv[6], lv[7]);
        WsH[0][sb + ((s0+0)^sx)] = wh.x;
        WsH[0][sb + ((s0+1)^sx)] = wh.y;
        WsH[0][sb + ((s0+2)^sx)] = wh.z;
        WsH[0][sb + ((s0+3)^sx)] = wh.w;
        WsL[0][sb + ((s0+0)^sx)] = wl.x;
        WsL[0][sb + ((s0+1)^sx)] = wl.y;
        WsL[0][sb + ((s0+2)^sx)] = wl.z;
        WsL[0][sb + ((s0+3)^sx)] = wl.w;
    }
    __syncthreads();

    int cur = 0;
    for (int kt = 0; kt < K; kt += 16) {
        const bool more = (kt + 16) < K;
        float4 na0, na1;
        uint4 nwh = uz, nwl = uz;
        if (more) {
            na0 = *(const float4*)(Ap + kt + 16);
            na1 = *(const float4*)(Ap + kt + 20);
            if (wok) {
                nwh = *(const uint4*)(Wph + kt + 16);
                nwl = *(const uint4*)(Wpl + kt + 16);
            }
        }

        // ---- compute k16 from stage cur ----
        uint32_t faH[4][4], faL[4][4], fbH[4][2], fbL[4][2];
#pragma unroll
        for (int mf = 0; mf < 4; mf++) {
            int r  = wm * 64 + mf * 16 + grp;           // r&7 == grp
            int r8 = (r + 8) * 8;
            int rb = r * 8;
            faH[mf][0] = AsH[cur][rb + (qid ^ grp)];
            faH[mf][1] = AsH[cur][r8 + (qid ^ grp)];
            faH[mf][2] = AsH[cur][rb + ((qid + 4) ^ grp)];
            faH[mf][3] = AsH[cur][r8 + ((qid + 4) ^ grp)];
            faL[mf][0] = AsL[cur][rb + (qid ^ grp)];
            faL[mf][1] = AsL[cur][r8 + (qid ^ grp)];
            faL[mf][2] = AsL[cur][rb + ((qid + 4) ^ grp)];
            faL[mf][3] = AsL[cur][r8 + ((qid + 4) ^ grp)];
        }
#pragma unroll
        for (int nf = 0; nf < 4; nf++) {
            int r  = wn * 32 + nf * 8 + grp;
            int rb = r * 8;
            fbH[nf][0] = WsH[cur][rb + (qid ^ grp)];
            fbH[nf][1] = WsH[cur][rb + ((qid + 4) ^ grp)];
            fbL[nf][0] = WsL[cur][rb + (qid ^ grp)];
            fbL[nf][1] = WsL[cur][rb + ((qid + 4) ^ grp)];
        }
#pragma unroll
        for (int mf = 0; mf < 4; mf++)
#pragma unroll
            for (int nf = 0; nf < 4; nf++) {
                mma16(accH[mf][nf], faH[mf], fbH[nf]);
                mma16(accL[mf][nf], faH[mf], fbL[nf]);
                mma16(accL[mf][nf], faL[mf], fbH[nf]);
            }

        // ---- stage next tile ----
        if (more) {
            const int nxt = cur ^ 1;
            float av[8] = {na0.x, na0.y, na0.z, na0.w, na1.x, na1.y, na1.z, na1.w};
            float hv[8], lv[8];
#pragma unroll
            for (int c = 0; c < 8; c++) {
                __half hh = __float2half_rn(av[c]);
                hv[c] = __half2float(hh);
                lv[c] = (av[c] - hv[c]) * 2048.0f;
            }
            AsH[nxt][sb + ((s0+0)^sx)] = pack2(hv[0], hv[1]);
            AsH[nxt][sb + ((s0+1)^sx)] = pack2(hv[2], hv[3]);
            AsH[nxt][sb + ((s0+2)^sx)] = pack2(hv[4], hv[5]);
            AsH[nxt][sb + ((s0+3)^sx)] = pack2(hv[6], hv[7]);
            AsL[nxt][sb + ((s0+0)^sx)] = pack2(lv[0], lv[1]);
            AsL[nxt][sb + ((s0+1)^sx)] = pack2(lv[2], lv[3]);
            AsL[nxt][sb + ((s0+2)^sx)] = pack2(lv[4], lv[5]);
            AsL[nxt][sb + ((s0+3)^sx)] = pack2(lv[6], lv[7]);
            WsH[nxt][sb + ((s0+0)^sx)] = nwh.x;
            WsH[nxt][sb + ((s0+1)^sx)] = nwh.y;
            WsH[nxt][sb + ((s0+2)^sx)] = nwh.z;
            WsH[nxt][sb + ((s0+3)^sx)] = nwh.w;
            WsL[nxt][sb + ((s0+0)^sx)] = nwl.x;
            WsL[nxt][sb + ((s0+1)^sx)] = nwl.y;
            WsL[nxt][sb + ((s0+2)^sx)] = nwl.z;
            WsL[nxt][sb + ((s0+3)^sx)] = nwl.w;
        }
        __syncthreads();
        cur ^= 1;
    }

    // ---- epilogue: acc = accH + accL/2048 + bias ----
    const int nwbase = n0 + wn * 32;
    float bv[4][2];
#pragma unroll
    for (int nf = 0; nf < 4; nf++) {
        int n = nwbase + nf * 8 + qid * 2;
        bv[nf][0] = (n < N) ? bias[n] : 0.f;
        bv[nf][1] = (n + 1 < N) ? bias[n + 1] : 0.f;
    }
#pragma unroll
    for (int mf = 0; mf < 4; mf++) {
#pragma unroll
        for (int half = 0; half < 2; half++) {
            long m  = m0 + wm * 64 + mf * 16 + grp + half * 8;
            long bb = m >> 11, ll = m & 2047;
            float* Cp = C + bb * cBS + (ll + cPad) * (long)N;
#pragma unroll
            for (int nf = 0; nf < 4; nf++) {
                int n = nwbase + nf * 8 + qid * 2;
                if (n < N) {
                    float v0 = accH[mf][nf][half*2+0] + accL[mf][nf][half*2+0] * INV2048 + bv[nf][0];
                    float v1 = accH[mf][nf][half*2+1] + accL[mf][nf][half*2+1] * INV2048 + bv[nf][1];
                    if (relu) { v0 = fmaxf(v0, 0.f); v1 = fmaxf(v1, 0.f); }
                    *(float2*)(Cp + n) = make_float2(v0, v1);
                }
            }
        }
    }
}

// ------------------- fp16 1x GEMM ------------------------------------------
__global__ __launch_bounds__(256, 2) void gemm16_fast_k(
    const float* __restrict__ A, const __half* __restrict__ Wh,
    const float* __restrict__ bias, float* __restrict__ C,
    int N, int K, long aBS, int aRS, long cBS, int cPad, int relu)
{
    __shared__ uint32_t As[2][1024];
    __shared__ uint32_t Ws[2][1024];

    const int t    = threadIdx.x;
    const int m0   = blockIdx.y * 128;
    const int n0   = blockIdx.x * 128;
    const int lane = t & 31, warp = t >> 5;
    const int wm   = warp >> 2, wn = warp & 3;
    const int grp  = lane >> 2, qid = lane & 3;

    const int srow = t >> 1;
    const int sh   = t & 1;
    long mA = m0 + srow;
    long bbA = mA >> 11, llA = mA & 2047;
    const float* Ap = A + bbA * aBS + llA * (long)aRS + sh * 8;

    const int nrow = n0 + srow;
    const bool wok = nrow < N;
    const __half* Wph = Wh + (long)nrow * K + sh * 8;

    float acc[4][4][4];
#pragma unroll
    for (int i = 0; i < 4; i++)
#pragma unroll
        for (int j = 0; j < 4; j++)
#pragma unroll
            for (int c = 0; c < 4; c++) acc[i][j][c] = 0.f;

    const int sb = srow * 8;
    const int sx = srow & 7;
    const int s0 = sh * 4;
    const uint4 uz = make_uint4(0u, 0u, 0u, 0u);

    // prologue
    {
        float4 a0 = *(const float4*)(Ap);
        float4 a1 = *(const float4*)(Ap + 4);
        uint4 wv = wok ? *(const uint4*)(Wph) : uz;
        As[0][sb + ((s0+0)^sx)] = pack2(a0.x, a0.y);
        As[0][sb + ((s0+1)^sx)] = pack2(a0.z, a0.w);
        As[0][sb + ((s0+2)^sx)] = pack2(a1.x, a1.y);
        As[0][sb + ((s0+3)^sx)] = pack2(a1.z, a1.w);
        Ws[0][sb + ((s0+0)^sx)] = wv.x;
        Ws[0][sb + ((s0+1)^sx)] = wv.y;
        Ws[0][sb + ((s0+2)^sx)] = wv.z;
        Ws[0][sb + ((s0+3)^sx)] = wv.w;
    }
    __syncthreads();

    int cur = 0;
    for (int kt = 0; kt < K; kt += 16) {
        const bool more = (kt + 16) < K;
        float4 na0, na1;
        uint4 nw = uz;
        if (more) {
            na0 = *(const float4*)(Ap + kt + 16);
            na1 = *(const float4*)(Ap + kt + 20);
            if (wok) nw = *(const uint4*)(Wph + kt + 16);
        }

        uint32_t fa[4][4], fb[4][2];
#pragma unroll
        for (int mf = 0; mf < 4; mf++) {
            int r  = wm * 64 + mf * 16 + grp;
            int rb = r * 8;
            int r8 = (r + 8) * 8;
            fa[mf][0] = As[cur][rb + (qid ^ grp)];
            fa[mf][1] = As[cur][r8 + (qid ^ grp)];
            fa[mf][2] = As[cur][rb + ((qid + 4) ^ grp)];
            fa[mf][3] = As[cur][r8 + ((qid + 4) ^ grp)];
        }
#pragma unroll
        for (int nf = 0; nf < 4; nf++) {
            int rb = (wn * 32 + nf * 8 + grp) * 8;
            fb[nf][0] = Ws[cur][rb + (qid ^ grp)];
            fb[nf][1] = Ws[cur][rb + ((qid + 4) ^ grp)];
        }
#pragma unroll
        for (int mf = 0; mf < 4; mf++)
#pragma unroll
            for (int nf = 0; nf < 4; nf++)
                mma16(acc[mf][nf], fa[mf], fb[nf]);

        if (more) {
            const int nxt = cur ^ 1;
            As[nxt][sb + ((s0+0)^sx)] = pack2(na0.x, na0.y);
            As[nxt][sb + ((s0+1)^sx)] = pack2(na0.z, na0.w);
            As[nxt][sb + ((s0+2)^sx)] = pack2(na1.x, na1.y);
            As[nxt][sb + ((s0+3)^sx)] = pack2(na1.z, na1.w);
            Ws[nxt][sb + ((s0+0)^sx)] = nw.x;
            Ws[nxt][sb + ((s0+1)^sx)] = nw.y;
            Ws[nxt][sb + ((s0+2)^sx)] = nw.z;
            Ws[nxt][sb + ((s0+3)^sx)] = nw.w;
        }
        __syncthreads();
        cur ^= 1;
    }

    // epilogue
    const int nwbase = n0 + wn * 32;
    float bv[4][2];
#pragma unroll
    for (int nf = 0; nf < 4; nf++) {
        int n = nwbase + nf * 8 + qid * 2;
        bv[nf][0] = (n < N) ? bias[n] : 0.f;
        bv[nf][1] = (n + 1 < N) ? bias[n + 1] : 0.f;
    }
#pragma unroll
    for (int mf = 0; mf < 4; mf++) {
#pragma unroll
        for (int half = 0; half < 2; half++) {
            long m  = m0 + wm * 64 + mf * 16 + grp + half * 8;
            long bb = m >> 11, ll = m & 2047;
            float* Cp = C + bb * cBS + (ll + cPad) * (long)N;
#pragma unroll
            for (int nf = 0; nf < 4; nf++) {
                int n = nwbase + nf * 8 + qid * 2;
                if (n < N) {
                    float v0 = acc[mf][nf][half*2+0] + bv[nf][0];
                    float v1 = acc[mf][nf][half*2+1] + bv[nf][1];
                    if (relu) { v0 = fmaxf(v0, 0.f); v1 = fmaxf(v1, 0.f); }
                    *(float2*)(Cp + n) = make_float2(v0, v1);
                }
            }
        }
    }
}

// --------------------------- VQ argmin + loss --------------------------------
__global__ __launch_bounds__(256) void argmin_k(
    const float* __restrict__ S, const float* __restrict__ ZE,
    int* __restrict__ codes, float* __restrict__ codesF,
    float* __restrict__ partials)
{
    int lane = threadIdx.x & 31;
    int wid  = threadIdx.x >> 5;
    int m    = blockIdx.x * 8 + wid;

    const float* Sp = S + (long)m * KCODE;
    float best = 3.4e38f;
    int   bi   = KCODE;
#pragma unroll
    for (int i = 0; i < 16; i++) {
        int c = lane + i * 32;
        float v = Sp[c];
        if (v < best) { best = v; bi = c; }
    }
#pragma unroll
    for (int off = 16; off; off >>= 1) {
        float ob = __shfl_down_sync(0xffffffff, best, off);
        int   oi = __shfl_down_sync(0xffffffff, bi, off);
        if (ob < best || (ob == best && oi < bi)) { best = ob; bi = oi; }
    }

    const float* Zp = ZE + (long)m * DCODE;
    float zn = 0.f;
#pragma unroll
    for (int i = 0; i < 2; i++) {
        float v = Zp[lane + i * 32];
        zn = fmaf(v, v, zn);
    }
#pragma unroll
    for (int off = 16; off; off >>= 1)
        zn += __shfl_down_sync(0xffffffff, zn, off);

    __shared__ float sPart[8];
    if (lane == 0) {
        codes[m] = bi;
        if (codesF) codesF[m] = (float)bi;
        sPart[wid] = zn + best;
    }
    __syncthreads();
    if (threadIdx.x == 0) {
        float s = 0.f;
        for (int i = 0; i < 8; i++) s += sPart[i];
        partials[blockIdx.x] = s;
    }
}

__global__ void loss_k(const float* __restrict__ partials, float* __restrict__ out) {
    __shared__ float sh[256];
    float s = 0.f;
    for (int i = threadIdx.x; i < 4096; i += 256) s += partials[i];
    sh[threadIdx.x] = s;
    __syncthreads();
    for (int off = 128; off; off >>= 1) {
        if (threadIdx.x < off) sh[threadIdx.x] += sh[threadIdx.x + off];
        __syncthreads();
    }
    if (threadIdx.x == 0)
        out[0] = 0.1f * sh[0] / (float)(MROWS * DCODE);
}

// ------------------------------- launch -------------------------------------
static void* symp(const void* s) {
    void* p = nullptr;
    cudaGetSymbolAddress(&p, s);
    return p;
}

static void run_split(const float* A, const __half* Wh, const __half* Wl,
                      const float* bias, float* C, int N, int K,
                      long aBS, int aRS, long cBS, int cPad, int relu)
{
    dim3 grid((N + 127) / 128, MROWS / 128);
    gemm16_split_k<<<grid, 256>>>(A, Wh, Wl, bias, C, N, K, aBS, aRS, cBS, cPad, relu);
}

static void run_fast(const float* A, const __half* Wh, const float* bias, float* C,
                     int M, int N, int K, long aBS, int aRS,
                     long cBS, int cPad, int relu)
{
    dim3 grid((N + 127) / 128, M / 128);
    gemm16_fast_k<<<grid, 256>>>(A, Wh, bias, C, N, K, aBS, aRS, cBS, cPad, relu);
}

extern "C" void kernel_launch(void* const* d_in, const int* in_sizes, int n_in,
                              void* d_out, int out_size)
{
    const int*   x        = (const int*)  d_in[0];
    const float* tokenEmb = (const float*)d_in[1];
    const float* ew1 = (const float*)d_in[2];  const float* eb1 = (const float*)d_in[3];
    const float* ew2 = (const float*)d_in[4];  const float* eb2 = (const float*)d_in[5];
    const float* ew3 = (const float*)d_in[6];  const float* eb3 = (const float*)d_in[7];
    const float* cb  = (const float*)d_in[8];
    const float* dw1 = (const float*)d_in[9];  const float* db1 = (const float*)d_in[10];
    const float* dw2 = (const float*)d_in[11]; const float* db2 = (const float*)d_in[12];
    const float* dw3 = (const float*)d_in[13]; const float* db3 = (const float*)d_in[14];
    const float* outW = (const float*)d_in[15];
    const float* outB = (const float*)d_in[16];

    float* out = (float*)d_out;

    float* P0  = (float*)symp(g_P0);   float* H1  = (float*)symp(g_H1);
    float* H2  = (float*)symp(g_H2);   float* ZE  = (float*)symp(g_ZE);
    float* S   = (float*)symp(g_S);    int*   CODES = (int*)symp(g_CODES);
    float* T   = (float*)symp(g_T);
    float* HD1 = (float*)symp(g_HD1);  float* HD2 = (float*)symp(g_HD2);
    float* HD3 = (float*)symp(g_HD3);  float* PART = (float*)symp(g_PART);
    __half* W1h = (__half*)symp(g_W1h);  __half* W1l = (__half*)symp(g_W1l);
    __half* W2h = (__half*)symp(g_W2h);  __half* W2l = (__half*)symp(g_W2l);
    __half* W3h = (__half*)symp(g_W3h);  __half* W3l = (__half*)symp(g_W3l);
    __half* CBh = (__half*)symp(g_CBh);  __half* CBl = (__half*)symp(g_CBl);
    float*  CNRM = (float*)symp(g_CNRM);
    __half* DW1h = (__half*)symp(g_DW1h); __half* DW2h = (__half*)symp(g_DW2h);
    __half* DW3h = (__half*)symp(g_DW3h); __half* OWh  = (__half*)symp(g_OWh);

    // ---- weight prepack (half [n][k]; hi+scaled-lo for encoder/VQ) ----
    pack_k3h<<<(HID * EMB * 3 + 255) / 256, 256>>>(ew1, W1h, W1l, HID, EMB);
    pack_k3h<<<(HID * HID * 3 + 255) / 256, 256>>>(ew2, W2h, W2l, HID, HID);
    pack_cvt<<<(DCODE * HID + 255) / 256, 256>>>(ew3, W3h, W3l, DCODE * HID);
    pack_cbh<<<KCODE / 8, 256>>>(cb, CBh, CBl, CNRM);
    pack_cvt<<<(HID * DCODE + 255) / 256, 256>>>(dw1, DW1h, nullptr, HID * DCODE);
    pack_k3h<<<(HID * HID * 3 + 255) / 256, 256>>>(dw2, DW2h, nullptr, HID, HID);
    pack_cvt<<<(EMB * HID + 255) / 256, 256>>>(dw3, DW3h, nullptr, EMB * HID);
    pack_cvt<<<(VOCAB * EMB + 255) / 256, 256>>>(outW, OWh, nullptr, VOCAB * EMB);

    // ---- embedding; zero pad rows of padded HID buffers ----
    embed_k<<<(BATCH * LPAD * EMB + 255) / 256, 256>>>(x, tokenEmb, P0);
    zeropad_k<<<(BATCH * 2 * HID * 2 + 255) / 256, 256>>>(H1, HD1);

    // ---- dec-conv1 table: T = relu(cb @ DW1 + db1), 512x256 ----
    run_fast(cb, DW1h, db1, T, KCODE, HID, DCODE, 0, DCODE, 0, 0, 1);

    // ---- encoder (fp16 hi/lo split: fp32-class, keeps VQ codes exact) ----
    run_split(P0, W1h, W1l, eb1, H1, HID, 3 * EMB,
              (long)LPAD * EMB, EMB, (long)LPAD * HID, 1, 1);
    run_split(H1, W2h, W2l, eb2, H2, HID, 3 * HID,
              (long)LPAD * HID, HID, (long)SEQL * HID, 0, 1);
    run_split(H2, W3h, W3l, eb3, ZE, DCODE, HID,
              (long)SEQL * HID, HID, (long)SEQL * DCODE, 0, 0);

    // ---- VQ scores (-2 z.c + |c|^2) + argmin + loss ----
    run_split(ZE, CBh, CBl, CNRM, S, KCODE, DCODE,
              (long)SEQL * DCODE, DCODE, (long)SEQL * KCODE, 0, 0);

    const long LOGN = (long)MROWS * VOCAB;
    bool full_out = ((long)out_size >= LOGN + 1 + MROWS);
    float* codesF = full_out ? (out + LOGN + 1) : nullptr;
    argmin_k<<<MROWS / 8, 256>>>(S, ZE, CODES, codesF, PART);
    if (full_out) loss_k<<<1, 256>>>(PART, out + LOGN);

    // ---- decoder: gather dec-conv1 rows from table, then fp16 GEMMs ----
    gather_k<<<(MROWS * (HID / 4)) / 256, 256>>>(T, CODES, HD1);
    run_fast(HD1, DW2h, db2, HD2, MROWS, HID, 3 * HID,
             (long)LPAD * HID, HID, (long)SEQL * HID, 0, 1);
    run_fast(HD2, DW3h, db3, HD3, MROWS, EMB, HID,
             (long)SEQL * HID, HID, (long)SEQL * EMB, 0, 1);

    // ---- vocab projection straight into d_out ----
    run_fast(HD3, OWh, outB, out, MROWS, VOCAB, EMB,
             (long)SEQL * EMB, EMB, (long)SEQL * VOCAB, 0, 0);
}